// round 1
// baseline (speedup 1.0000x reference)
#include <cuda_runtime.h>
#include <cstdint>

// Problem constants (fixed by the reference)
#define S_DIM 8192
#define B_DIM 8192
#define ENC 256
#define C_DIM 25
#define K_RANK 25   // 0-based rank -> 26th smallest

// ------------------------------------------------------------------
// Scratch (device globals: allocation-free per harness rules)
// ------------------------------------------------------------------
__device__ float g_d2[(size_t)S_DIM * B_DIM];   // 268 MB distance^2 matrix
__device__ float g_e2[B_DIM];
__device__ float g_q2[S_DIM];
__device__ float g_maxg[B_DIM];
__device__ unsigned char g_grp[B_DIM];

// ------------------------------------------------------------------
// Kernel 1: per-row ||e||^2, argmax/max over categorical
// one block (256 threads) per row b
// ------------------------------------------------------------------
__global__ void prep_kernel(const float* __restrict__ enc,
                            const float* __restrict__ cat) {
    int b = blockIdx.x;
    int t = threadIdx.x;

    float v = enc[(size_t)b * ENC + t];
    float sq = v * v;
    #pragma unroll
    for (int o = 16; o > 0; o >>= 1) sq += __shfl_xor_sync(0xFFFFFFFFu, sq, o);

    __shared__ float ws[8];
    if ((t & 31) == 0) ws[t >> 5] = sq;
    __syncthreads();
    if (t == 0) {
        float s = 0.f;
        #pragma unroll
        for (int i = 0; i < 8; i++) s += ws[i];
        g_e2[b] = s;
    }

    if (t < 32) {
        float mv = -1e30f;
        int   mi = 0x7FFFFFFF;
        if (t < C_DIM) { mv = cat[(size_t)b * C_DIM + t]; mi = t; }
        #pragma unroll
        for (int o = 16; o > 0; o >>= 1) {
            float ov = __shfl_xor_sync(0xFFFFFFFFu, mv, o);
            int   oi = __shfl_xor_sync(0xFFFFFFFFu, mi, o);
            if (ov > mv || (ov == mv && oi < mi)) { mv = ov; mi = oi; }
        }
        if (t == 0) { g_maxg[b] = mv; g_grp[b] = (unsigned char)mi; }
    }
}

// ------------------------------------------------------------------
// Kernel 2: q2[s] = e2[idxs[s]]
// ------------------------------------------------------------------
__global__ void q2_kernel(const int* __restrict__ idxs) {
    int s = blockIdx.x * blockDim.x + threadIdx.x;
    if (s < S_DIM) g_q2[s] = g_e2[idxs[s]];
}

// ------------------------------------------------------------------
// Kernel 3: SIMT fp32 GEMM -> d2[s][b] = q2[s] + e2[b] - 2 * q.e
// 128x128 tiles, BK=16, 256 threads, 8x8 per thread.
// ------------------------------------------------------------------
#define BM 128
#define BN 128
#define BK 16
#define TM 8
#define TN 8
#define AS_STRIDE (BM + 4)   // 132: kills transposed-store bank conflicts

__global__ __launch_bounds__(256, 2)
void dist_gemm(const float* __restrict__ enc, const int* __restrict__ idxs) {
    __shared__ float As[BK][AS_STRIDE];
    __shared__ float Bs[BK][AS_STRIDE];
    __shared__ int rowidx[BM];

    const int tid  = threadIdx.x;
    const int brow = blockIdx.y * BM;   // s range
    const int bcol = blockIdx.x * BN;   // b range

    if (tid < BM) rowidx[tid] = idxs[brow + tid];
    __syncthreads();

    const int tx = tid & 15;
    const int ty = tid >> 4;

    float acc[TM][TN];
    #pragma unroll
    for (int i = 0; i < TM; i++)
        #pragma unroll
        for (int j = 0; j < TN; j++) acc[i][j] = 0.f;

    for (int k0 = 0; k0 < ENC; k0 += BK) {
        // Load A (gathered) and B tiles: 128 rows x 16 k each.
        #pragma unroll
        for (int it = 0; it < 2; it++) {
            int f  = tid + it * 256;      // 0..511
            int r  = f >> 2;              // 0..127
            int c4 = (f & 3) << 2;        // 0,4,8,12

            float4 a = *reinterpret_cast<const float4*>(
                &enc[(size_t)rowidx[r] * ENC + k0 + c4]);
            As[c4 + 0][r] = a.x; As[c4 + 1][r] = a.y;
            As[c4 + 2][r] = a.z; As[c4 + 3][r] = a.w;

            float4 b = *reinterpret_cast<const float4*>(
                &enc[(size_t)(bcol + r) * ENC + k0 + c4]);
            Bs[c4 + 0][r] = b.x; Bs[c4 + 1][r] = b.y;
            Bs[c4 + 2][r] = b.z; Bs[c4 + 3][r] = b.w;
        }
        __syncthreads();

        #pragma unroll
        for (int k = 0; k < BK; k++) {
            float ra[TM], rb[TN];
            float4 a0 = *reinterpret_cast<const float4*>(&As[k][ty * TM]);
            float4 a1 = *reinterpret_cast<const float4*>(&As[k][ty * TM + 4]);
            ra[0]=a0.x; ra[1]=a0.y; ra[2]=a0.z; ra[3]=a0.w;
            ra[4]=a1.x; ra[5]=a1.y; ra[6]=a1.z; ra[7]=a1.w;
            float4 b0 = *reinterpret_cast<const float4*>(&Bs[k][tx * TN]);
            float4 b1 = *reinterpret_cast<const float4*>(&Bs[k][tx * TN + 4]);
            rb[0]=b0.x; rb[1]=b0.y; rb[2]=b0.z; rb[3]=b0.w;
            rb[4]=b1.x; rb[5]=b1.y; rb[6]=b1.z; rb[7]=b1.w;
            #pragma unroll
            for (int i = 0; i < TM; i++)
                #pragma unroll
                for (int j = 0; j < TN; j++)
                    acc[i][j] = fmaf(ra[i], rb[j], acc[i][j]);
        }
        __syncthreads();
    }

    // Epilogue: d2 = q2 + e2 - 2*dot, clamp >= 0, vectorized store.
    const int orow0 = brow + ty * TM;
    const int ocol0 = bcol + tx * TN;
    float e2c[TN];
    #pragma unroll
    for (int j = 0; j < TN; j++) e2c[j] = g_e2[ocol0 + j];

    #pragma unroll
    for (int i = 0; i < TM; i++) {
        float q2v = g_q2[orow0 + i];
        float4 o0, o1;
        o0.x = fmaxf(q2v + e2c[0] - 2.f * acc[i][0], 0.f);
        o0.y = fmaxf(q2v + e2c[1] - 2.f * acc[i][1], 0.f);
        o0.z = fmaxf(q2v + e2c[2] - 2.f * acc[i][2], 0.f);
        o0.w = fmaxf(q2v + e2c[3] - 2.f * acc[i][3], 0.f);
        o1.x = fmaxf(q2v + e2c[4] - 2.f * acc[i][4], 0.f);
        o1.y = fmaxf(q2v + e2c[5] - 2.f * acc[i][5], 0.f);
        o1.z = fmaxf(q2v + e2c[6] - 2.f * acc[i][6], 0.f);
        o1.w = fmaxf(q2v + e2c[7] - 2.f * acc[i][7], 0.f);
        float* orow = &g_d2[(size_t)(orow0 + i) * B_DIM + ocol0];
        *reinterpret_cast<float4*>(orow)     = o0;
        *reinterpret_cast<float4*>(orow + 4) = o1;
    }
}

// ------------------------------------------------------------------
// Kernel 4: per-row exact radix select (rank 25) on fp32 bit patterns,
// then masked cluster bincount + entropy. One 256-thread block per row.
// All d2 >= 0  =>  uint32 bit order == float order.
// ------------------------------------------------------------------
__global__ __launch_bounds__(256)
void select_kernel(const int* __restrict__ idxs, float* __restrict__ out) {
    const int s   = blockIdx.x;
    const int tid = threadIdx.x;

    __shared__ unsigned int vbits[B_DIM];      // 32 KB
    __shared__ unsigned int hist[256];
    __shared__ int counts[C_DIM];
    __shared__ unsigned int sh_pref;
    __shared__ int sh_rank;

    // Load row (vectorized)
    const uint4* row4 = reinterpret_cast<const uint4*>(g_d2 + (size_t)s * B_DIM);
    uint4* v4 = reinterpret_cast<uint4*>(vbits);
    for (int i = tid; i < B_DIM / 4; i += 256) v4[i] = row4[i];

    if (tid == 0) { sh_pref = 0u; sh_rank = K_RANK; }
    __syncthreads();

    // 4-pass radix select, MSB -> LSB
    #pragma unroll
    for (int pass = 0; pass < 4; pass++) {
        const int shift = 24 - pass * 8;
        hist[tid] = 0u;
        __syncthreads();

        const unsigned int pref  = sh_pref;
        const unsigned int pmask = (pass == 0) ? 0u : (0xFFFFFFFFu << (shift + 8));

        for (int i = tid; i < B_DIM; i += 256) {
            unsigned int v = vbits[i];
            if ((v & pmask) == pref)
                atomicAdd(&hist[(v >> shift) & 0xFF], 1u);
        }
        __syncthreads();

        if (tid < 32) {
            int base = tid * 8;
            unsigned int partial = 0;
            #pragma unroll
            for (int j = 0; j < 8; j++) partial += hist[base + j];
            unsigned int cum = partial;
            #pragma unroll
            for (int o = 1; o < 32; o <<= 1) {
                unsigned int x = __shfl_up_sync(0xFFFFFFFFu, cum, o);
                if (tid >= o) cum += x;
            }
            int rank = sh_rank;
            unsigned int excl = cum - partial;
            unsigned int bal = __ballot_sync(0xFFFFFFFFu,
                rank >= (int)excl && rank < (int)cum);
            int lane = __ffs(bal) - 1;
            if (tid == lane) {
                int r = rank - (int)excl;
                int bin = base;
                for (;;) {
                    unsigned int h = hist[bin];
                    if (r < (int)h) break;
                    r -= (int)h;
                    bin++;
                }
                sh_pref = pref | ((unsigned int)bin << shift);
                sh_rank = r;
            }
        }
        __syncthreads();
    }

    const unsigned int kbits = sh_pref;  // exact bits of 26th-smallest d2

    if (tid < C_DIM) counts[tid] = 0;
    __syncthreads();

    // Masked bincount: strict less-than, matches reference `dists < kth`
    for (int i = tid; i < B_DIM; i += 256) {
        if (vbits[i] < kbits) atomicAdd(&counts[g_grp[i]], 1);
    }
    __syncthreads();

    if (tid == 0) {
        int n = 0;
        #pragma unroll
        for (int c = 0; c < C_DIM; c++) n += counts[c];
        float inv = 1.0f / (float)n;
        float purity = 0.f;
        #pragma unroll
        for (int c = 0; c < C_DIM; c++) {
            float p = (float)counts[c] * inv;
            purity -= p * logf(p + 1e-5f);
        }
        out[s] = purity * g_maxg[idxs[s]];
    }
}

// ------------------------------------------------------------------
// Launch
// ------------------------------------------------------------------
extern "C" void kernel_launch(void* const* d_in, const int* in_sizes, int n_in,
                              void* d_out, int out_size) {
    const float* enc  = (const float*)d_in[0];   // [8192, 256] f32
    const float* cat  = (const float*)d_in[1];   // [8192, 25]  f32
    const int*   idxs = (const int*)d_in[2];     // [8192]      i32
    float* out = (float*)d_out;                  // [8192]      f32

    prep_kernel<<<B_DIM, 256>>>(enc, cat);
    q2_kernel<<<S_DIM / 256, 256>>>(idxs);

    dim3 grid(B_DIM / BN, S_DIM / BM);
    dist_gemm<<<grid, 256>>>(enc, idxs);

    select_kernel<<<S_DIM, 256>>>(idxs, out);
}

// round 3
// speedup vs baseline: 1.0874x; 1.0874x over previous
#include <cuda_runtime.h>
#include <cstdint>

// Problem constants
#define S_DIM 8192
#define B_DIM 8192
#define ENC 256
#define C_DIM 25
#define K_RANK 25   // 0-based rank -> 26th smallest

// ------------------------------------------------------------------
// Scratch (device globals; allocation-free per harness rules)
// ------------------------------------------------------------------
__device__ __align__(256) float g_d2[(size_t)S_DIM * B_DIM];   // 268 MB
__device__ __align__(256) float g_ehi[(size_t)B_DIM * ENC];    // tf32 hi of encodings
__device__ __align__(256) float g_elo[(size_t)B_DIM * ENC];    // tf32 lo residual
__device__ __align__(256) float g_qhi[(size_t)S_DIM * ENC];    // gathered query rows
__device__ __align__(256) float g_qlo[(size_t)S_DIM * ENC];
__device__ float g_e2[B_DIM];
__device__ float g_q2[S_DIM];
__device__ float g_maxg[B_DIM];
__device__ unsigned char g_grp[B_DIM];

// ------------------------------------------------------------------
// Base-ISA PTX helpers (NO 'a'-suffix features: harness targets compute_103)
// ------------------------------------------------------------------
__device__ __forceinline__ uint32_t smem_u32(const void* p) {
    uint32_t a;
    asm("{ .reg .u64 t; cvta.to.shared.u64 t, %1; cvt.u32.u64 %0, t; }"
        : "=r"(a) : "l"(p));
    return a;
}
__device__ __forceinline__ float tf32_rn(float x) {
    uint32_t u;
    asm("cvt.rna.tf32.f32 %0, %1;" : "=r"(u) : "f"(x));
    return __uint_as_float(u);
}
__device__ __forceinline__ void cp16(uint32_t dst, const void* src) {
    asm volatile("cp.async.cg.shared.global [%0], [%1], 16;" :: "r"(dst), "l"(src));
}
__device__ __forceinline__ void ldsm4(uint32_t* r, uint32_t addr) {
    asm volatile("ldmatrix.sync.aligned.m8n8.x4.shared.b16 {%0,%1,%2,%3}, [%4];"
                 : "=r"(r[0]), "=r"(r[1]), "=r"(r[2]), "=r"(r[3]) : "r"(addr));
}
__device__ __forceinline__ void mma_tf32(float* c, const uint32_t* a, const uint32_t* b) {
    asm volatile(
        "mma.sync.aligned.m16n8k8.row.col.f32.tf32.tf32.f32 "
        "{%0,%1,%2,%3}, {%4,%5,%6,%7}, {%8,%9}, {%0,%1,%2,%3};"
        : "+f"(c[0]), "+f"(c[1]), "+f"(c[2]), "+f"(c[3])
        : "r"(a[0]), "r"(a[1]), "r"(a[2]), "r"(a[3]), "r"(b[0]), "r"(b[1]));
}
#define SWZ(o) ((o) ^ (((o) >> 3) & 0x70))

// ------------------------------------------------------------------
// Kernel 1: e2, argmax/max, tf32 hi/lo split.  One block per b-row.
// ------------------------------------------------------------------
__global__ void prep_kernel(const float* __restrict__ enc,
                            const float* __restrict__ cat) {
    int b = blockIdx.x;
    int t = threadIdx.x;

    float v  = enc[(size_t)b * ENC + t];
    float hi = tf32_rn(v);
    float lo = tf32_rn(v - hi);
    g_ehi[(size_t)b * ENC + t] = hi;
    g_elo[(size_t)b * ENC + t] = lo;

    float sq = v * v;
    #pragma unroll
    for (int o = 16; o > 0; o >>= 1) sq += __shfl_xor_sync(0xFFFFFFFFu, sq, o);

    __shared__ float ws[8];
    if ((t & 31) == 0) ws[t >> 5] = sq;
    __syncthreads();
    if (t == 0) {
        float s = 0.f;
        #pragma unroll
        for (int i = 0; i < 8; i++) s += ws[i];
        g_e2[b] = s;
    }

    if (t < 32) {
        float mv = -1e30f;
        int   mi = 0x7FFFFFFF;
        if (t < C_DIM) { mv = cat[(size_t)b * C_DIM + t]; mi = t; }
        #pragma unroll
        for (int o = 16; o > 0; o >>= 1) {
            float ov = __shfl_xor_sync(0xFFFFFFFFu, mv, o);
            int   oi = __shfl_xor_sync(0xFFFFFFFFu, mi, o);
            if (ov > mv || (ov == mv && oi < mi)) { mv = ov; mi = oi; }
        }
        if (t == 0) { g_maxg[b] = mv; g_grp[b] = (unsigned char)mi; }
    }
}

// ------------------------------------------------------------------
// Kernel 2: gather q rows (hi/lo) + q2
// ------------------------------------------------------------------
__global__ void gather_kernel(const int* __restrict__ idxs) {
    int s = blockIdx.x, t = threadIdx.x;
    int idx = idxs[s];
    const float4* sh = reinterpret_cast<const float4*>(&g_ehi[(size_t)idx * ENC]);
    const float4* sl = reinterpret_cast<const float4*>(&g_elo[(size_t)idx * ENC]);
    float4* dh = reinterpret_cast<float4*>(&g_qhi[(size_t)s * ENC]);
    float4* dl = reinterpret_cast<float4*>(&g_qlo[(size_t)s * ENC]);
    dh[t] = sh[t];
    dl[t] = sl[t];
    if (t == 0) g_q2[s] = g_e2[idx];
}

// ------------------------------------------------------------------
// Kernel 3: mma.sync tf32 3-term GEMM -> d2
//  CTA tile 128(M) x 256(N), K-chunk 32. Per chunk: tiles {Ahi,Alo,Bhi,Blo}.
//  8 warps, each 64x64, acc fp32. D = Ahi*Bhi + Ahi*Blo + Alo*Bhi.
// ------------------------------------------------------------------
#define BM 128
#define BN 256
#define BK 32
#define NCHUNK (ENC / BK)                 // 8
#define A_TILE (BM * 128)                 // 16 KB (128 rows x 128B)
#define B_TILE (BN * 128)                 // 32 KB
#define STAGE  (2 * A_TILE + 2 * B_TILE)  // 96 KB
#define GEMM_SMEM (2 * STAGE)             // 192 KB

__device__ __forceinline__ void load_stage(uint32_t st, int brow, int bcol,
                                           int k0, int tid) {
    // A tiles: 128 rows x 8 x 16B
    #pragma unroll
    for (int it = 0; it < 4; ++it) {
        int i = tid + it * 256;
        int r = i >> 3, ch = i & 7;
        uint32_t off = SWZ((uint32_t)(r * 128 + ch * 16));
        size_t go = (size_t)(brow + r) * ENC + k0 + ch * 4;
        cp16(st + off,          g_qhi + go);
        cp16(st + A_TILE + off, g_qlo + go);
    }
    // B tiles: 256 rows x 8 x 16B
    #pragma unroll
    for (int it = 0; it < 8; ++it) {
        int i = tid + it * 256;
        int r = i >> 3, ch = i & 7;
        uint32_t off = SWZ((uint32_t)(r * 128 + ch * 16));
        size_t go = (size_t)(bcol + r) * ENC + k0 + ch * 4;
        cp16(st + 2 * A_TILE + off,          g_ehi + go);
        cp16(st + 2 * A_TILE + B_TILE + off, g_elo + go);
    }
    asm volatile("cp.async.commit_group;" ::: "memory");
}

__global__ __launch_bounds__(256, 1)
void dist_gemm_mma() {
    extern __shared__ char dsm_raw[];
    __shared__ float e2s[BN];
    __shared__ float q2s[BM];

    const int tid    = threadIdx.x;
    const int lane   = tid & 31;
    const int wid    = tid >> 5;
    const int warp_m = wid & 1;        // 2 warps over M
    const int warp_n = wid >> 1;       // 4 warps over N
    const int brow   = blockIdx.y * BM;
    const int bcol   = blockIdx.x * BN;

    const uint32_t dsm = smem_u32(dsm_raw);

    for (int i = tid; i < BN; i += 256) e2s[i] = g_e2[bcol + i];
    for (int i = tid; i < BM; i += 256) q2s[i] = g_q2[brow + i];

    float acc[4][8][4];
    #pragma unroll
    for (int im = 0; im < 4; im++)
        #pragma unroll
        for (int j = 0; j < 8; j++)
            #pragma unroll
            for (int v = 0; v < 4; v++) acc[im][j][v] = 0.f;

    // ldmatrix per-lane address components (16B-row granularity)
    const int a_row  = warp_m * 64 + (lane & 15);        // + im*16
    const int a_kb   = (lane >> 4) << 4;                 // + ks*32
    const int b_row  = warp_n * 64 + ((lane >> 4) << 3) + (lane & 7);  // + jn*16
    const int b_kb   = ((lane >> 3) & 1) << 4;           // + ks*32

    load_stage(dsm,         brow, bcol, 0,  tid);
    load_stage(dsm + STAGE, brow, bcol, BK, tid);

    #pragma unroll
    for (int c = 0; c < NCHUNK; ++c) {
        if (c == NCHUNK - 1) asm volatile("cp.async.wait_group 0;" ::: "memory");
        else                 asm volatile("cp.async.wait_group 1;" ::: "memory");
        __syncthreads();

        const uint32_t st = dsm + (c & 1) * STAGE;

        #pragma unroll
        for (int ks = 0; ks < 4; ++ks) {
            uint32_t ahi[4][4], alo[4][4], bhi[8][2], blo[8][2];
            #pragma unroll
            for (int im = 0; im < 4; ++im) {
                uint32_t off = SWZ((uint32_t)((a_row + im * 16) * 128 + ks * 32 + a_kb));
                ldsm4(ahi[im], st + off);
                ldsm4(alo[im], st + A_TILE + off);
            }
            #pragma unroll
            for (int jn = 0; jn < 4; ++jn) {
                uint32_t off = SWZ((uint32_t)((b_row + jn * 16) * 128 + ks * 32 + b_kb));
                uint32_t rh[4], rl[4];
                ldsm4(rh, st + 2 * A_TILE + off);
                ldsm4(rl, st + 2 * A_TILE + B_TILE + off);
                bhi[2 * jn][0] = rh[0]; bhi[2 * jn][1] = rh[1];
                bhi[2 * jn + 1][0] = rh[2]; bhi[2 * jn + 1][1] = rh[3];
                blo[2 * jn][0] = rl[0]; blo[2 * jn][1] = rl[1];
                blo[2 * jn + 1][0] = rl[2]; blo[2 * jn + 1][1] = rl[3];
            }
            #pragma unroll
            for (int im = 0; im < 4; ++im)
                #pragma unroll
                for (int j = 0; j < 8; ++j) {
                    mma_tf32(acc[im][j], ahi[im], bhi[j]);
                    mma_tf32(acc[im][j], ahi[im], blo[j]);
                    mma_tf32(acc[im][j], alo[im], bhi[j]);
                }
        }
        __syncthreads();
        if (c + 2 < NCHUNK)
            load_stage(dsm + (c & 1) * STAGE, brow, bcol, (c + 2) * BK, tid);
    }

    // Epilogue: d2 = max(q2 + e2 - 2*acc, 0)
    #pragma unroll
    for (int im = 0; im < 4; ++im) {
        const int r0 = warp_m * 64 + im * 16 + (lane >> 2);
        const float q2a = q2s[r0];
        const float q2b = q2s[r0 + 8];
        #pragma unroll
        for (int j = 0; j < 8; ++j) {
            const int cl = warp_n * 64 + j * 8 + 2 * (lane & 3);
            const float e0 = e2s[cl], e1 = e2s[cl + 1];
            float2 oa, ob;
            oa.x = fmaxf(fmaf(-2.f, acc[im][j][0], q2a + e0), 0.f);
            oa.y = fmaxf(fmaf(-2.f, acc[im][j][1], q2a + e1), 0.f);
            ob.x = fmaxf(fmaf(-2.f, acc[im][j][2], q2b + e0), 0.f);
            ob.y = fmaxf(fmaf(-2.f, acc[im][j][3], q2b + e1), 0.f);
            *reinterpret_cast<float2*>(&g_d2[(size_t)(brow + r0) * B_DIM + bcol + cl]) = oa;
            *reinterpret_cast<float2*>(&g_d2[(size_t)(brow + r0 + 8) * B_DIM + bcol + cl]) = ob;
        }
    }
}

// ------------------------------------------------------------------
// Kernel 4: per-row radix select (rank 25) + masked bincount + entropy.
// Warp-aggregated histogram atomics (match_any) kill the pass-0 storm.
// ------------------------------------------------------------------
__global__ __launch_bounds__(256)
void select_kernel(const int* __restrict__ idxs, float* __restrict__ out) {
    const int s   = blockIdx.x;
    const int tid = threadIdx.x;

    __shared__ unsigned int vbits[B_DIM];      // 32 KB
    __shared__ unsigned int hist[256];
    __shared__ int counts[C_DIM];
    __shared__ unsigned int sh_pref;
    __shared__ int sh_rank;

    const uint4* row4 = reinterpret_cast<const uint4*>(g_d2 + (size_t)s * B_DIM);
    uint4* v4 = reinterpret_cast<uint4*>(vbits);
    for (int i = tid; i < B_DIM / 4; i += 256) v4[i] = row4[i];

    if (tid == 0) { sh_pref = 0u; sh_rank = K_RANK; }
    __syncthreads();

    #pragma unroll
    for (int pass = 0; pass < 4; pass++) {
        const int shift = 24 - pass * 8;
        hist[tid] = 0u;
        __syncthreads();

        const unsigned int pref  = sh_pref;
        const unsigned int pmask = (pass == 0) ? 0u : (0xFFFFFFFFu << (shift + 8));

        for (int i = tid; i < B_DIM; i += 256) {
            unsigned int v = vbits[i];
            if ((v & pmask) == pref) {
                int bin = (v >> shift) & 0xFF;
                unsigned int am = __activemask();
                unsigned int eq = __match_any_sync(am, bin);
                if ((int)(tid & 31) == __ffs(eq) - 1)
                    atomicAdd(&hist[bin], __popc(eq));
            }
        }
        __syncthreads();

        if (tid < 32) {
            int base = tid * 8;
            unsigned int partial = 0;
            #pragma unroll
            for (int j = 0; j < 8; j++) partial += hist[base + j];
            unsigned int cum = partial;
            #pragma unroll
            for (int o = 1; o < 32; o <<= 1) {
                unsigned int x = __shfl_up_sync(0xFFFFFFFFu, cum, o);
                if (tid >= o) cum += x;
            }
            int rank = sh_rank;
            unsigned int excl = cum - partial;
            unsigned int bal = __ballot_sync(0xFFFFFFFFu,
                rank >= (int)excl && rank < (int)cum);
            int lane = __ffs(bal) - 1;
            if (tid == lane) {
                int r = rank - (int)excl;
                int bin = base;
                for (;;) {
                    unsigned int h = hist[bin];
                    if (r < (int)h) break;
                    r -= (int)h;
                    bin++;
                }
                sh_pref = pref | ((unsigned int)bin << shift);
                sh_rank = r;
            }
        }
        __syncthreads();
    }

    const unsigned int kbits = sh_pref;

    if (tid < C_DIM) counts[tid] = 0;
    __syncthreads();

    for (int i = tid; i < B_DIM; i += 256) {
        if (vbits[i] < kbits) {
            int c = g_grp[i];
            unsigned int am = __activemask();
            unsigned int eq = __match_any_sync(am, c);
            if ((int)(tid & 31) == __ffs(eq) - 1)
                atomicAdd(&counts[c], __popc(eq));
        }
    }
    __syncthreads();

    if (tid == 0) {
        int n = 0;
        #pragma unroll
        for (int c = 0; c < C_DIM; c++) n += counts[c];
        float inv = 1.0f / (float)n;
        float purity = 0.f;
        #pragma unroll
        for (int c = 0; c < C_DIM; c++) {
            float p = (float)counts[c] * inv;
            purity -= p * logf(p + 1e-5f);
        }
        out[s] = purity * g_maxg[idxs[s]];
    }
}

// ------------------------------------------------------------------
// Launch
// ------------------------------------------------------------------
extern "C" void kernel_launch(void* const* d_in, const int* in_sizes, int n_in,
                              void* d_out, int out_size) {
    const float* enc  = (const float*)d_in[0];
    const float* cat  = (const float*)d_in[1];
    const int*   idxs = (const int*)d_in[2];
    float* out = (float*)d_out;

    static bool attr_done = false;
    if (!attr_done) {
        cudaFuncSetAttribute(dist_gemm_mma,
                             cudaFuncAttributeMaxDynamicSharedMemorySize, GEMM_SMEM);
        attr_done = true;
    }

    prep_kernel<<<B_DIM, 256>>>(enc, cat);
    gather_kernel<<<S_DIM, 64>>>(idxs);

    dim3 grid(B_DIM / BN, S_DIM / BM);
    dist_gemm_mma<<<grid, 256, GEMM_SMEM>>>();

    select_kernel<<<S_DIM, 256>>>(idxs, out);
}

// round 4
// speedup vs baseline: 1.7032x; 1.5663x over previous
#include <cuda_runtime.h>
#include <cuda_bf16.h>
#include <cstdint>

// Problem constants
#define S_DIM 8192
#define B_DIM 8192
#define ENC 256
#define C_DIM 25
#define K_RANK 25   // 0-based rank -> 26th smallest

// ------------------------------------------------------------------
// Scratch (device globals; allocation-free per harness rules)
// ------------------------------------------------------------------
__device__ __align__(256) float g_d2[(size_t)S_DIM * B_DIM];            // 268 MB
__device__ __align__(256) float g_ehi[(size_t)B_DIM * ENC];             // tf32(e)
__device__ __align__(256) float g_qhi[(size_t)S_DIM * ENC];             // gathered tf32(q)
__device__ __align__(256) __nv_bfloat16 g_ecA[(size_t)B_DIM * 2 * ENC]; // [qh16 | ql16] per b-row
__device__ __align__(256) __nv_bfloat16 g_ecB[(size_t)B_DIM * 2 * ENC]; // [el16 | eh16] per b-row
__device__ __align__(256) __nv_bfloat16 g_qcA[(size_t)S_DIM * 2 * ENC]; // gathered corr-A rows
__device__ float g_e2[B_DIM];
__device__ float g_q2[S_DIM];
__device__ float g_maxg[B_DIM];
__device__ unsigned char g_grp[B_DIM];

// ------------------------------------------------------------------
// Base-ISA PTX helpers (harness compiles via compute_103: NO 'a' features)
// ------------------------------------------------------------------
__device__ __forceinline__ uint32_t smem_u32(const void* p) {
    uint32_t a;
    asm("{ .reg .u64 t; cvta.to.shared.u64 t, %1; cvt.u32.u64 %0, t; }"
        : "=r"(a) : "l"(p));
    return a;
}
__device__ __forceinline__ float tf32_rn(float x) {
    uint32_t u;
    asm("cvt.rna.tf32.f32 %0, %1;" : "=r"(u) : "f"(x));
    return __uint_as_float(u);
}
__device__ __forceinline__ void cp16(uint32_t dst, const void* src) {
    asm volatile("cp.async.cg.shared.global [%0], [%1], 16;" :: "r"(dst), "l"(src));
}
__device__ __forceinline__ void ldsm4(uint32_t* r, uint32_t addr) {
    asm volatile("ldmatrix.sync.aligned.m8n8.x4.shared.b16 {%0,%1,%2,%3}, [%4];"
                 : "=r"(r[0]), "=r"(r[1]), "=r"(r[2]), "=r"(r[3]) : "r"(addr));
}
__device__ __forceinline__ void mma_tf32(float* c, const uint32_t* a, const uint32_t* b) {
    asm volatile(
        "mma.sync.aligned.m16n8k8.row.col.f32.tf32.tf32.f32 "
        "{%0,%1,%2,%3}, {%4,%5,%6,%7}, {%8,%9}, {%0,%1,%2,%3};"
        : "+f"(c[0]), "+f"(c[1]), "+f"(c[2]), "+f"(c[3])
        : "r"(a[0]), "r"(a[1]), "r"(a[2]), "r"(a[3]), "r"(b[0]), "r"(b[1]));
}
__device__ __forceinline__ void mma_bf16(float* c, const uint32_t* a, const uint32_t* b) {
    asm volatile(
        "mma.sync.aligned.m16n8k16.row.col.f32.bf16.bf16.f32 "
        "{%0,%1,%2,%3}, {%4,%5,%6,%7}, {%8,%9}, {%0,%1,%2,%3};"
        : "+f"(c[0]), "+f"(c[1]), "+f"(c[2]), "+f"(c[3])
        : "r"(a[0]), "r"(a[1]), "r"(a[2]), "r"(a[3]), "r"(b[0]), "r"(b[1]));
}
#define SWZ(o) ((o) ^ (((o) >> 3) & 0x70))

// ------------------------------------------------------------------
// Kernel 1: e2, argmax/max, tf32 + bf16 splits.  One block per b-row.
// ------------------------------------------------------------------
__global__ void prep_kernel(const float* __restrict__ enc,
                            const float* __restrict__ cat) {
    int b = blockIdx.x;
    int t = threadIdx.x;

    float v  = enc[(size_t)b * ENC + t];
    float hi = tf32_rn(v);
    float lo = v - hi;
    g_ehi[(size_t)b * ENC + t] = hi;
    __nv_bfloat16 h16 = __float2bfloat16(hi);
    __nv_bfloat16 l16 = __float2bfloat16(lo);
    g_ecA[(size_t)b * 2 * ENC + t]       = h16;   // qh16 slot
    g_ecA[(size_t)b * 2 * ENC + ENC + t] = l16;   // ql16 slot
    g_ecB[(size_t)b * 2 * ENC + t]       = l16;   // el16 slot
    g_ecB[(size_t)b * 2 * ENC + ENC + t] = h16;   // eh16 slot

    float sq = v * v;
    #pragma unroll
    for (int o = 16; o > 0; o >>= 1) sq += __shfl_xor_sync(0xFFFFFFFFu, sq, o);

    __shared__ float ws[8];
    if ((t & 31) == 0) ws[t >> 5] = sq;
    __syncthreads();
    if (t == 0) {
        float s = 0.f;
        #pragma unroll
        for (int i = 0; i < 8; i++) s += ws[i];
        g_e2[b] = s;
    }

    if (t < 32) {
        float mv = -1e30f;
        int   mi = 0x7FFFFFFF;
        if (t < C_DIM) { mv = cat[(size_t)b * C_DIM + t]; mi = t; }
        #pragma unroll
        for (int o = 16; o > 0; o >>= 1) {
            float ov = __shfl_xor_sync(0xFFFFFFFFu, mv, o);
            int   oi = __shfl_xor_sync(0xFFFFFFFFu, mi, o);
            if (ov > mv || (ov == mv && oi < mi)) { mv = ov; mi = oi; }
        }
        if (t == 0) { g_maxg[b] = mv; g_grp[b] = (unsigned char)mi; }
    }
}

// ------------------------------------------------------------------
// Kernel 2: gather q rows (tf32 + corrA) + q2
// ------------------------------------------------------------------
__global__ void gather_kernel(const int* __restrict__ idxs) {
    int s = blockIdx.x, t = threadIdx.x;   // 64 threads
    int idx = idxs[s];
    const float4* sh = reinterpret_cast<const float4*>(&g_ehi[(size_t)idx * ENC]);
    float4* dh = reinterpret_cast<float4*>(&g_qhi[(size_t)s * ENC]);
    dh[t] = sh[t];
    const uint4* sc = reinterpret_cast<const uint4*>(&g_ecA[(size_t)idx * 2 * ENC]);
    uint4* dc = reinterpret_cast<uint4*>(&g_qcA[(size_t)s * 2 * ENC]);
    dc[t] = sc[t];
    if (t == 0) g_q2[s] = g_e2[idx];
}

// ------------------------------------------------------------------
// Kernel 3: mixed tf32 + bf16 GEMM -> d2
//  CTA tile 128(M) x 256(N). Per chunk c: tf32 K=32 (main hi*hi) and
//  bf16 K=64 of the packed 512-dim correction ([qh|ql]*[el|eh]).
//  All tiles are 128B/row, SW128 swizzled -> identical ldmatrix paths.
// ------------------------------------------------------------------
#define BM 128
#define BN 256
#define NCHUNK 8
#define AF32_OFF 0
#define ACOR_OFF (128 * 128)                    // 16 KB
#define BF32_OFF (2 * 128 * 128)                // 32 KB
#define BCOR_OFF (BF32_OFF + 256 * 128)         // +32 KB
#define STAGE    (BCOR_OFF + 256 * 128)         // 96 KB
#define GEMM_SMEM (2 * STAGE)                   // 192 KB

__device__ __forceinline__ void load_stage(uint32_t st, int brow, int bcol,
                                           int c, int tid) {
    const char* qcA = reinterpret_cast<const char*>(g_qcA);
    const char* ecB = reinterpret_cast<const char*>(g_ecB);
    // A tiles: 128 rows x 8 x 16B each (f32-hi and bf16-corr)
    #pragma unroll
    for (int it = 0; it < 4; ++it) {
        int i = tid + it * 256;
        int r = i >> 3, ch = i & 7;
        uint32_t off = SWZ((uint32_t)(r * 128 + ch * 16));
        cp16(st + AF32_OFF + off, g_qhi + (size_t)(brow + r) * ENC + c * 32 + ch * 4);
        cp16(st + ACOR_OFF + off, qcA + (size_t)(brow + r) * 1024 + c * 128 + ch * 16);
    }
    // B tiles: 256 rows x 8 x 16B each
    #pragma unroll
    for (int it = 0; it < 8; ++it) {
        int i = tid + it * 256;
        int r = i >> 3, ch = i & 7;
        uint32_t off = SWZ((uint32_t)(r * 128 + ch * 16));
        cp16(st + BF32_OFF + off, g_ehi + (size_t)(bcol + r) * ENC + c * 32 + ch * 4);
        cp16(st + BCOR_OFF + off, ecB + (size_t)(bcol + r) * 1024 + c * 128 + ch * 16);
    }
    asm volatile("cp.async.commit_group;" ::: "memory");
}

__global__ __launch_bounds__(256, 1)
void dist_gemm_mma() {
    extern __shared__ char dsm_raw[];
    __shared__ float e2s[BN];
    __shared__ float q2s[BM];

    const int tid    = threadIdx.x;
    const int lane   = tid & 31;
    const int wid    = tid >> 5;
    const int warp_m = wid & 1;        // 2 warps over M
    const int warp_n = wid >> 1;       // 4 warps over N
    const int brow   = blockIdx.y * BM;
    const int bcol   = blockIdx.x * BN;

    const uint32_t dsm = smem_u32(dsm_raw);

    for (int i = tid; i < BN; i += 256) e2s[i] = g_e2[bcol + i];
    for (int i = tid; i < BM; i += 256) q2s[i] = g_q2[brow + i];

    float acc[4][8][4];
    #pragma unroll
    for (int im = 0; im < 4; im++)
        #pragma unroll
        for (int j = 0; j < 8; j++)
            #pragma unroll
            for (int v = 0; v < 4; v++) acc[im][j][v] = 0.f;

    // ldmatrix per-lane address components (16B units within 128B rows)
    const int a_row = warp_m * 64 + (lane & 15);                       // + im*16
    const int a_kb  = (lane >> 4) << 4;                                // + ks*32
    const int b_row = warp_n * 64 + ((lane >> 4) << 3) + (lane & 7);   // + jn*16
    const int b_kb  = ((lane >> 3) & 1) << 4;                          // + ks*32

    load_stage(dsm,         brow, bcol, 0, tid);
    load_stage(dsm + STAGE, brow, bcol, 1, tid);

    #pragma unroll
    for (int c = 0; c < NCHUNK; ++c) {
        if (c == NCHUNK - 1) asm volatile("cp.async.wait_group 0;" ::: "memory");
        else                 asm volatile("cp.async.wait_group 1;" ::: "memory");
        __syncthreads();

        const uint32_t st = dsm + (c & 1) * STAGE;

        #pragma unroll
        for (int ks = 0; ks < 4; ++ks) {
            uint32_t ahi[4][4], aco[4][4], bhi[8][2], bco[8][2];
            #pragma unroll
            for (int im = 0; im < 4; ++im) {
                uint32_t off = SWZ((uint32_t)((a_row + im * 16) * 128 + ks * 32 + a_kb));
                ldsm4(ahi[im], st + AF32_OFF + off);
                ldsm4(aco[im], st + ACOR_OFF + off);
            }
            #pragma unroll
            for (int jn = 0; jn < 4; ++jn) {
                uint32_t off = SWZ((uint32_t)((b_row + jn * 16) * 128 + ks * 32 + b_kb));
                uint32_t rh[4], rc[4];
                ldsm4(rh, st + BF32_OFF + off);
                ldsm4(rc, st + BCOR_OFF + off);
                bhi[2 * jn][0] = rh[0]; bhi[2 * jn][1] = rh[1];
                bhi[2 * jn + 1][0] = rh[2]; bhi[2 * jn + 1][1] = rh[3];
                bco[2 * jn][0] = rc[0]; bco[2 * jn][1] = rc[1];
                bco[2 * jn + 1][0] = rc[2]; bco[2 * jn + 1][1] = rc[3];
            }
            #pragma unroll
            for (int im = 0; im < 4; ++im)
                #pragma unroll
                for (int j = 0; j < 8; ++j) {
                    mma_tf32(acc[im][j], ahi[im], bhi[j]);
                    mma_bf16(acc[im][j], aco[im], bco[j]);
                }
        }
        __syncthreads();
        if (c + 2 < NCHUNK)
            load_stage(dsm + (c & 1) * STAGE, brow, bcol, c + 2, tid);
    }

    // Epilogue: d2 = max(q2 + e2 - 2*acc, 0)
    #pragma unroll
    for (int im = 0; im < 4; ++im) {
        const int r0 = warp_m * 64 + im * 16 + (lane >> 2);
        const float q2a = q2s[r0];
        const float q2b = q2s[r0 + 8];
        #pragma unroll
        for (int j = 0; j < 8; ++j) {
            const int cl = warp_n * 64 + j * 8 + 2 * (lane & 3);
            const float e0 = e2s[cl], e1 = e2s[cl + 1];
            float2 oa, ob;
            oa.x = fmaxf(fmaf(-2.f, acc[im][j][0], q2a + e0), 0.f);
            oa.y = fmaxf(fmaf(-2.f, acc[im][j][1], q2a + e1), 0.f);
            ob.x = fmaxf(fmaf(-2.f, acc[im][j][2], q2b + e0), 0.f);
            ob.y = fmaxf(fmaf(-2.f, acc[im][j][3], q2b + e1), 0.f);
            *reinterpret_cast<float2*>(&g_d2[(size_t)(brow + r0) * B_DIM + bcol + cl]) = oa;
            *reinterpret_cast<float2*>(&g_d2[(size_t)(brow + r0 + 8) * B_DIM + bcol + cl]) = ob;
        }
    }
}

// ------------------------------------------------------------------
// Kernel 4 (v3): single 2048-bin histogram pass over float bits >>20,
// candidate collect in kth bin, O(m^2) exact mini-select, bincount.
// Plain atomics (match_any regressed in R3).
// ------------------------------------------------------------------
#define NBINS 2048
#define CAND_CAP 2048

__global__ __launch_bounds__(256)
void select_kernel(const int* __restrict__ idxs, float* __restrict__ out) {
    const int s   = blockIdx.x;
    const int tid = threadIdx.x;

    __shared__ unsigned int vbits[B_DIM];        // 32 KB
    __shared__ unsigned int hist[NBINS];         // 8 KB
    __shared__ unsigned int cand[CAND_CAP];      // 8 KB
    __shared__ unsigned int warp_sums[8];
    __shared__ int counts[C_DIM];
    __shared__ unsigned int sh_bin, sh_below, sh_cnt, sh_kbits;

    // Load row
    const uint4* row4 = reinterpret_cast<const uint4*>(g_d2 + (size_t)s * B_DIM);
    uint4* v4 = reinterpret_cast<uint4*>(vbits);
    #pragma unroll
    for (int i = 0; i < B_DIM / 4 / 256; i++) v4[tid + i * 256] = row4[tid + i * 256];

    #pragma unroll
    for (int i = 0; i < NBINS / 256; i++) hist[tid + i * 256] = 0u;
    if (tid == 0) sh_cnt = 0u;
    __syncthreads();

    // Histogram on top 12 value bits (sign always 0 after clamp)
    #pragma unroll
    for (int i = 0; i < B_DIM / 256; i++)
        atomicAdd(&hist[vbits[tid + i * 256] >> 20], 1u);
    __syncthreads();

    // Block scan over 256 partials (8 bins each); locate kth bin.
    {
        const int base = tid * (NBINS / 256);
        unsigned int part = 0;
        #pragma unroll
        for (int j = 0; j < NBINS / 256; j++) part += hist[base + j];

        unsigned int cum = part;
        #pragma unroll
        for (int o = 1; o < 32; o <<= 1) {
            unsigned int x = __shfl_up_sync(0xFFFFFFFFu, cum, o);
            if ((tid & 31) >= o) cum += x;
        }
        if ((tid & 31) == 31) warp_sums[tid >> 5] = cum;
        __syncthreads();
        if (tid < 8) {
            unsigned int w = warp_sums[tid];
            #pragma unroll
            for (int o = 1; o < 8; o <<= 1) {
                unsigned int x = __shfl_up_sync(0xFFu, w, o);
                if (tid >= o) w += x;
            }
            warp_sums[tid] = w;
        }
        __syncthreads();
        unsigned int excl = cum - part + ((tid >> 5) ? warp_sums[(tid >> 5) - 1] : 0u);
        if ((int)excl <= K_RANK && K_RANK < (int)(excl + part)) {
            unsigned int run = excl;
            #pragma unroll
            for (int j = 0; j < NBINS / 256; j++) {
                unsigned int h = hist[base + j];
                if (K_RANK >= (int)run && K_RANK < (int)(run + h)) {
                    sh_bin = base + j;
                    sh_below = run;
                }
                run += h;
            }
        }
    }
    __syncthreads();

    // Collect candidates in the kth bin
    const unsigned int tbin = sh_bin;
    #pragma unroll
    for (int i = 0; i < B_DIM / 256; i++) {
        unsigned int v = vbits[tid + i * 256];
        if ((v >> 20) == tbin) {
            unsigned int p = atomicAdd(&sh_cnt, 1u);
            if (p < CAND_CAP) cand[p] = v;
        }
    }
    __syncthreads();

    // Exact select of residual rank r among m candidates
    const int m = (int)min(sh_cnt, (unsigned int)CAND_CAP);
    const int r = K_RANK - (int)sh_below;
    for (int i = tid; i < m; i += 256) {
        unsigned int vi = cand[i];
        int lo = 0, eq = 0;
        for (int j = 0; j < m; j++) {
            unsigned int vj = cand[j];
            lo += (vj < vi);
            eq += (vj == vi);
        }
        if (lo <= r && r < lo + eq) sh_kbits = vi;
    }
    if (tid < C_DIM) counts[tid] = 0;
    __syncthreads();

    // Masked bincount (strict less-than, matches reference)
    const unsigned int kbits = sh_kbits;
    #pragma unroll
    for (int i = 0; i < B_DIM / 256; i++) {
        unsigned int v = vbits[tid + i * 256];
        if (v < kbits) atomicAdd(&counts[g_grp[tid + i * 256]], 1);
    }
    __syncthreads();

    if (tid == 0) {
        int n = 0;
        #pragma unroll
        for (int c = 0; c < C_DIM; c++) n += counts[c];
        float inv = 1.0f / (float)n;
        float purity = 0.f;
        #pragma unroll
        for (int c = 0; c < C_DIM; c++) {
            float p = (float)counts[c] * inv;
            purity -= p * logf(p + 1e-5f);
        }
        out[s] = purity * g_maxg[idxs[s]];
    }
}

// ------------------------------------------------------------------
// Launch
// ------------------------------------------------------------------
extern "C" void kernel_launch(void* const* d_in, const int* in_sizes, int n_in,
                              void* d_out, int out_size) {
    const float* enc  = (const float*)d_in[0];
    const float* cat  = (const float*)d_in[1];
    const int*   idxs = (const int*)d_in[2];
    float* out = (float*)d_out;

    static bool attr_done = false;
    if (!attr_done) {
        cudaFuncSetAttribute(dist_gemm_mma,
                             cudaFuncAttributeMaxDynamicSharedMemorySize, GEMM_SMEM);
        attr_done = true;
    }

    prep_kernel<<<B_DIM, 256>>>(enc, cat);
    gather_kernel<<<S_DIM, 64>>>(idxs);

    dim3 grid(B_DIM / BN, S_DIM / BM);
    dist_gemm_mma<<<grid, 256, GEMM_SMEM>>>();

    select_kernel<<<S_DIM, 256>>>(idxs, out);
}

// round 5
// speedup vs baseline: 1.8066x; 1.0607x over previous
#include <cuda_runtime.h>
#include <cuda_bf16.h>
#include <cstdint>

// Problem constants
#define S_DIM 8192
#define B_DIM 8192
#define ENC 256
#define C_DIM 25
#define K_RANK 25   // 0-based rank -> 26th smallest

// ------------------------------------------------------------------
// Scratch (device globals; allocation-free per harness rules)
// ------------------------------------------------------------------
__device__ __align__(256) float g_d2[(size_t)S_DIM * B_DIM];            // 268 MB
__device__ __align__(256) float g_ehi[(size_t)B_DIM * ENC];             // tf32(e)
__device__ __align__(256) float g_qhi[(size_t)S_DIM * ENC];             // gathered tf32(q)
__device__ __align__(256) __nv_bfloat16 g_ecA[(size_t)B_DIM * 2 * ENC]; // [qh16 | ql16] per b-row
__device__ __align__(256) __nv_bfloat16 g_ecB[(size_t)B_DIM * 2 * ENC]; // [el16 | eh16] per b-row
__device__ __align__(256) __nv_bfloat16 g_qcA[(size_t)S_DIM * 2 * ENC]; // gathered corr-A rows
__device__ float g_e2[B_DIM];
__device__ float g_q2[S_DIM];
__device__ float g_maxg[B_DIM];
__device__ unsigned char g_grp[B_DIM];

// ------------------------------------------------------------------
// Base-ISA PTX helpers (harness compiles via compute_103: NO 'a' features)
// ------------------------------------------------------------------
__device__ __forceinline__ uint32_t smem_u32(const void* p) {
    uint32_t a;
    asm("{ .reg .u64 t; cvta.to.shared.u64 t, %1; cvt.u32.u64 %0, t; }"
        : "=r"(a) : "l"(p));
    return a;
}
__device__ __forceinline__ float tf32_rn(float x) {
    uint32_t u;
    asm("cvt.rna.tf32.f32 %0, %1;" : "=r"(u) : "f"(x));
    return __uint_as_float(u);
}
__device__ __forceinline__ void cp16(uint32_t dst, const void* src) {
    asm volatile("cp.async.cg.shared.global [%0], [%1], 16;" :: "r"(dst), "l"(src));
}
__device__ __forceinline__ void ldsm4(uint32_t* r, uint32_t addr) {
    asm volatile("ldmatrix.sync.aligned.m8n8.x4.shared.b16 {%0,%1,%2,%3}, [%4];"
                 : "=r"(r[0]), "=r"(r[1]), "=r"(r[2]), "=r"(r[3]) : "r"(addr));
}
__device__ __forceinline__ void mma_tf32(float* c, const uint32_t* a, const uint32_t* b) {
    asm volatile(
        "mma.sync.aligned.m16n8k8.row.col.f32.tf32.tf32.f32 "
        "{%0,%1,%2,%3}, {%4,%5,%6,%7}, {%8,%9}, {%0,%1,%2,%3};"
        : "+f"(c[0]), "+f"(c[1]), "+f"(c[2]), "+f"(c[3])
        : "r"(a[0]), "r"(a[1]), "r"(a[2]), "r"(a[3]), "r"(b[0]), "r"(b[1]));
}
__device__ __forceinline__ void mma_bf16(float* c, const uint32_t* a, const uint32_t* b) {
    asm volatile(
        "mma.sync.aligned.m16n8k16.row.col.f32.bf16.bf16.f32 "
        "{%0,%1,%2,%3}, {%4,%5,%6,%7}, {%8,%9}, {%0,%1,%2,%3};"
        : "+f"(c[0]), "+f"(c[1]), "+f"(c[2]), "+f"(c[3])
        : "r"(a[0]), "r"(a[1]), "r"(a[2]), "r"(a[3]), "r"(b[0]), "r"(b[1]));
}
#define SWZ(o) ((o) ^ (((o) >> 3) & 0x70))

// ------------------------------------------------------------------
// Kernel 1: e2, argmax/max, tf32 + bf16 splits.  One block per b-row.
// ------------------------------------------------------------------
__global__ void prep_kernel(const float* __restrict__ enc,
                            const float* __restrict__ cat) {
    int b = blockIdx.x;
    int t = threadIdx.x;

    float v  = enc[(size_t)b * ENC + t];
    float hi = tf32_rn(v);
    float lo = v - hi;
    g_ehi[(size_t)b * ENC + t] = hi;
    __nv_bfloat16 h16 = __float2bfloat16(hi);
    __nv_bfloat16 l16 = __float2bfloat16(lo);
    g_ecA[(size_t)b * 2 * ENC + t]       = h16;   // qh16 slot
    g_ecA[(size_t)b * 2 * ENC + ENC + t] = l16;   // ql16 slot
    g_ecB[(size_t)b * 2 * ENC + t]       = l16;   // el16 slot
    g_ecB[(size_t)b * 2 * ENC + ENC + t] = h16;   // eh16 slot

    float sq = v * v;
    #pragma unroll
    for (int o = 16; o > 0; o >>= 1) sq += __shfl_xor_sync(0xFFFFFFFFu, sq, o);

    __shared__ float ws[8];
    if ((t & 31) == 0) ws[t >> 5] = sq;
    __syncthreads();
    if (t == 0) {
        float s = 0.f;
        #pragma unroll
        for (int i = 0; i < 8; i++) s += ws[i];
        g_e2[b] = s;
    }

    if (t < 32) {
        float mv = -1e30f;
        int   mi = 0x7FFFFFFF;
        if (t < C_DIM) { mv = cat[(size_t)b * C_DIM + t]; mi = t; }
        #pragma unroll
        for (int o = 16; o > 0; o >>= 1) {
            float ov = __shfl_xor_sync(0xFFFFFFFFu, mv, o);
            int   oi = __shfl_xor_sync(0xFFFFFFFFu, mi, o);
            if (ov > mv || (ov == mv && oi < mi)) { mv = ov; mi = oi; }
        }
        if (t == 0) { g_maxg[b] = mv; g_grp[b] = (unsigned char)mi; }
    }
}

// ------------------------------------------------------------------
// Kernel 2: gather q rows (tf32 + corrA) + q2
// ------------------------------------------------------------------
__global__ void gather_kernel(const int* __restrict__ idxs) {
    int s = blockIdx.x, t = threadIdx.x;   // 64 threads
    int idx = idxs[s];
    const float4* sh = reinterpret_cast<const float4*>(&g_ehi[(size_t)idx * ENC]);
    float4* dh = reinterpret_cast<float4*>(&g_qhi[(size_t)s * ENC]);
    dh[t] = sh[t];
    const uint4* sc = reinterpret_cast<const uint4*>(&g_ecA[(size_t)idx * 2 * ENC]);
    uint4* dc = reinterpret_cast<uint4*>(&g_qcA[(size_t)s * 2 * ENC]);
    dc[t] = sc[t];
    if (t == 0) g_q2[s] = g_e2[idx];
}

// ------------------------------------------------------------------
// Kernel 3: mixed tf32 + bf16 GEMM -> d2  (unchanged from R4: proven)
// ------------------------------------------------------------------
#define BM 128
#define BN 256
#define NCHUNK 8
#define AF32_OFF 0
#define ACOR_OFF (128 * 128)                    // 16 KB
#define BF32_OFF (2 * 128 * 128)                // 32 KB
#define BCOR_OFF (BF32_OFF + 256 * 128)         // +32 KB
#define STAGE    (BCOR_OFF + 256 * 128)         // 96 KB
#define GEMM_SMEM (2 * STAGE)                   // 192 KB

__device__ __forceinline__ void load_stage(uint32_t st, int brow, int bcol,
                                           int c, int tid) {
    const char* qcA = reinterpret_cast<const char*>(g_qcA);
    const char* ecB = reinterpret_cast<const char*>(g_ecB);
    #pragma unroll
    for (int it = 0; it < 4; ++it) {
        int i = tid + it * 256;
        int r = i >> 3, ch = i & 7;
        uint32_t off = SWZ((uint32_t)(r * 128 + ch * 16));
        cp16(st + AF32_OFF + off, g_qhi + (size_t)(brow + r) * ENC + c * 32 + ch * 4);
        cp16(st + ACOR_OFF + off, qcA + (size_t)(brow + r) * 1024 + c * 128 + ch * 16);
    }
    #pragma unroll
    for (int it = 0; it < 8; ++it) {
        int i = tid + it * 256;
        int r = i >> 3, ch = i & 7;
        uint32_t off = SWZ((uint32_t)(r * 128 + ch * 16));
        cp16(st + BF32_OFF + off, g_ehi + (size_t)(bcol + r) * ENC + c * 32 + ch * 4);
        cp16(st + BCOR_OFF + off, ecB + (size_t)(bcol + r) * 1024 + c * 128 + ch * 16);
    }
    asm volatile("cp.async.commit_group;" ::: "memory");
}

__global__ __launch_bounds__(256, 1)
void dist_gemm_mma() {
    extern __shared__ char dsm_raw[];
    __shared__ float e2s[BN];
    __shared__ float q2s[BM];

    const int tid    = threadIdx.x;
    const int lane   = tid & 31;
    const int wid    = tid >> 5;
    const int warp_m = wid & 1;
    const int warp_n = wid >> 1;
    const int brow   = blockIdx.y * BM;
    const int bcol   = blockIdx.x * BN;

    const uint32_t dsm = smem_u32(dsm_raw);

    for (int i = tid; i < BN; i += 256) e2s[i] = g_e2[bcol + i];
    for (int i = tid; i < BM; i += 256) q2s[i] = g_q2[brow + i];

    float acc[4][8][4];
    #pragma unroll
    for (int im = 0; im < 4; im++)
        #pragma unroll
        for (int j = 0; j < 8; j++)
            #pragma unroll
            for (int v = 0; v < 4; v++) acc[im][j][v] = 0.f;

    const int a_row = warp_m * 64 + (lane & 15);
    const int a_kb  = (lane >> 4) << 4;
    const int b_row = warp_n * 64 + ((lane >> 4) << 3) + (lane & 7);
    const int b_kb  = ((lane >> 3) & 1) << 4;

    load_stage(dsm,         brow, bcol, 0, tid);
    load_stage(dsm + STAGE, brow, bcol, 1, tid);

    #pragma unroll
    for (int c = 0; c < NCHUNK; ++c) {
        if (c == NCHUNK - 1) asm volatile("cp.async.wait_group 0;" ::: "memory");
        else                 asm volatile("cp.async.wait_group 1;" ::: "memory");
        __syncthreads();

        const uint32_t st = dsm + (c & 1) * STAGE;

        #pragma unroll
        for (int ks = 0; ks < 4; ++ks) {
            uint32_t ahi[4][4], aco[4][4], bhi[8][2], bco[8][2];
            #pragma unroll
            for (int im = 0; im < 4; ++im) {
                uint32_t off = SWZ((uint32_t)((a_row + im * 16) * 128 + ks * 32 + a_kb));
                ldsm4(ahi[im], st + AF32_OFF + off);
                ldsm4(aco[im], st + ACOR_OFF + off);
            }
            #pragma unroll
            for (int jn = 0; jn < 4; ++jn) {
                uint32_t off = SWZ((uint32_t)((b_row + jn * 16) * 128 + ks * 32 + b_kb));
                uint32_t rh[4], rc[4];
                ldsm4(rh, st + BF32_OFF + off);
                ldsm4(rc, st + BCOR_OFF + off);
                bhi[2 * jn][0] = rh[0]; bhi[2 * jn][1] = rh[1];
                bhi[2 * jn + 1][0] = rh[2]; bhi[2 * jn + 1][1] = rh[3];
                bco[2 * jn][0] = rc[0]; bco[2 * jn][1] = rc[1];
                bco[2 * jn + 1][0] = rc[2]; bco[2 * jn + 1][1] = rc[3];
            }
            #pragma unroll
            for (int im = 0; im < 4; ++im)
                #pragma unroll
                for (int j = 0; j < 8; ++j) {
                    mma_tf32(acc[im][j], ahi[im], bhi[j]);
                    mma_bf16(acc[im][j], aco[im], bco[j]);
                }
        }
        __syncthreads();
        if (c + 2 < NCHUNK)
            load_stage(dsm + (c & 1) * STAGE, brow, bcol, c + 2, tid);
    }

    #pragma unroll
    for (int im = 0; im < 4; ++im) {
        const int r0 = warp_m * 64 + im * 16 + (lane >> 2);
        const float q2a = q2s[r0];
        const float q2b = q2s[r0 + 8];
        #pragma unroll
        for (int j = 0; j < 8; ++j) {
            const int cl = warp_n * 64 + j * 8 + 2 * (lane & 3);
            const float e0 = e2s[cl], e1 = e2s[cl + 1];
            float2 oa, ob;
            oa.x = fmaxf(fmaf(-2.f, acc[im][j][0], q2a + e0), 0.f);
            oa.y = fmaxf(fmaf(-2.f, acc[im][j][1], q2a + e1), 0.f);
            ob.x = fmaxf(fmaf(-2.f, acc[im][j][2], q2b + e0), 0.f);
            ob.y = fmaxf(fmaf(-2.f, acc[im][j][3], q2b + e1), 0.f);
            *reinterpret_cast<float2*>(&g_d2[(size_t)(brow + r0) * B_DIM + bcol + cl]) = oa;
            *reinterpret_cast<float2*>(&g_d2[(size_t)(brow + r0 + 8) * B_DIM + bcol + cl]) = ob;
        }
    }
}

// ------------------------------------------------------------------
// Kernel 4 (v4): register-resident select.
//  - Row lives in 32 regs/thread across ALL phases (no vbits SMEM).
//  - 2048-bin histogram on float bits >>20, block scan -> kth bin.
//  - Candidates (values only) -> exact O(m^2) mini-select -> kbits.
//  - Count phase: labels loaded from global ONLY on the ~25 hits.
// ------------------------------------------------------------------
#define NBINS 2048
#define CAND_CAP 1024
#define VPT 8   // uint4 per thread (32 values)

__global__ __launch_bounds__(256)
void select_kernel(const int* __restrict__ idxs, float* __restrict__ out) {
    const int s   = blockIdx.x;
    const int tid = threadIdx.x;

    __shared__ unsigned int hist[NBINS];         // 8 KB
    __shared__ unsigned int cand[CAND_CAP];      // 4 KB
    __shared__ unsigned int warp_sums[8];
    __shared__ int counts[C_DIM];
    __shared__ unsigned int sh_bin, sh_below, sh_cnt, sh_kbits;

    // Load row into registers (coalesced uint4)
    const uint4* row4 = reinterpret_cast<const uint4*>(g_d2 + (size_t)s * B_DIM);
    uint4 v[VPT];
    #pragma unroll
    for (int k = 0; k < VPT; k++) v[k] = row4[tid + k * 256];

    #pragma unroll
    for (int i = 0; i < NBINS / 256; i++) hist[tid + i * 256] = 0u;
    if (tid == 0) sh_cnt = 0u;
    __syncthreads();

    // Histogram on top 12 value bits
    #pragma unroll
    for (int k = 0; k < VPT; k++) {
        atomicAdd(&hist[v[k].x >> 20], 1u);
        atomicAdd(&hist[v[k].y >> 20], 1u);
        atomicAdd(&hist[v[k].z >> 20], 1u);
        atomicAdd(&hist[v[k].w >> 20], 1u);
    }
    __syncthreads();

    // Block scan over 256 partials (8 bins each); locate kth bin.
    {
        const int base = tid * (NBINS / 256);
        unsigned int part = 0;
        #pragma unroll
        for (int j = 0; j < NBINS / 256; j++) part += hist[base + j];

        unsigned int cum = part;
        #pragma unroll
        for (int o = 1; o < 32; o <<= 1) {
            unsigned int x = __shfl_up_sync(0xFFFFFFFFu, cum, o);
            if ((tid & 31) >= o) cum += x;
        }
        if ((tid & 31) == 31) warp_sums[tid >> 5] = cum;
        __syncthreads();
        if (tid < 8) {
            unsigned int w = warp_sums[tid];
            #pragma unroll
            for (int o = 1; o < 8; o <<= 1) {
                unsigned int x = __shfl_up_sync(0xFFu, w, o);
                if (tid >= o) w += x;
            }
            warp_sums[tid] = w;
        }
        __syncthreads();
        unsigned int excl = cum - part + ((tid >> 5) ? warp_sums[(tid >> 5) - 1] : 0u);
        if ((int)excl <= K_RANK && K_RANK < (int)(excl + part)) {
            unsigned int run = excl;
            #pragma unroll
            for (int j = 0; j < NBINS / 256; j++) {
                unsigned int h = hist[base + j];
                if (K_RANK >= (int)run && K_RANK < (int)(run + h)) {
                    sh_bin = base + j;
                    sh_below = run;
                }
                run += h;
            }
        }
    }
    __syncthreads();

    // Collect candidate values in the kth bin (from registers)
    const unsigned int tbin = sh_bin;
    #pragma unroll
    for (int k = 0; k < VPT; k++) {
        unsigned int vv[4] = {v[k].x, v[k].y, v[k].z, v[k].w};
        #pragma unroll
        for (int j = 0; j < 4; j++) {
            if ((vv[j] >> 20) == tbin) {
                unsigned int p = atomicAdd(&sh_cnt, 1u);
                if (p < CAND_CAP) cand[p] = vv[j];
            }
        }
    }
    __syncthreads();

    // Exact select of residual rank r among m candidates
    const int m = (int)min(sh_cnt, (unsigned int)CAND_CAP);
    const int r = K_RANK - (int)sh_below;
    for (int i = tid; i < m; i += 256) {
        unsigned int vi = cand[i];
        int lo = 0, eq = 0;
        for (int j = 0; j < m; j++) {
            unsigned int vj = cand[j];
            lo += (vj < vi);
            eq += (vj == vi);
        }
        if (lo <= r && r < lo + eq) sh_kbits = vi;
    }
    if (tid < C_DIM) counts[tid] = 0;
    __syncthreads();

    // Masked bincount: label fetched from global ONLY on hit (~25/row)
    const unsigned int kbits = sh_kbits;
    #pragma unroll
    for (int k = 0; k < VPT; k++) {
        const int base_idx = 4 * (tid + k * 256);
        unsigned int vv[4] = {v[k].x, v[k].y, v[k].z, v[k].w};
        #pragma unroll
        for (int j = 0; j < 4; j++) {
            if (vv[j] < kbits)
                atomicAdd(&counts[g_grp[base_idx + j]], 1);
        }
    }
    __syncthreads();

    if (tid == 0) {
        int n = 0;
        #pragma unroll
        for (int c = 0; c < C_DIM; c++) n += counts[c];
        float inv = 1.0f / (float)n;
        float purity = 0.f;
        #pragma unroll
        for (int c = 0; c < C_DIM; c++) {
            float p = (float)counts[c] * inv;
            purity -= p * logf(p + 1e-5f);
        }
        out[s] = purity * g_maxg[idxs[s]];
    }
}

// ------------------------------------------------------------------
// Launch
// ------------------------------------------------------------------
extern "C" void kernel_launch(void* const* d_in, const int* in_sizes, int n_in,
                              void* d_out, int out_size) {
    const float* enc  = (const float*)d_in[0];
    const float* cat  = (const float*)d_in[1];
    const int*   idxs = (const int*)d_in[2];
    float* out = (float*)d_out;

    static bool attr_done = false;
    if (!attr_done) {
        cudaFuncSetAttribute(dist_gemm_mma,
                             cudaFuncAttributeMaxDynamicSharedMemorySize, GEMM_SMEM);
        attr_done = true;
    }

    prep_kernel<<<B_DIM, 256>>>(enc, cat);
    gather_kernel<<<S_DIM, 64>>>(idxs);

    dim3 grid(B_DIM / BN, S_DIM / BM);
    dist_gemm_mma<<<grid, 256, GEMM_SMEM>>>();

    select_kernel<<<S_DIM, 256>>>(idxs, out);
}

// round 6
// speedup vs baseline: 1.8455x; 1.0216x over previous
#include <cuda_runtime.h>
#include <cuda_bf16.h>
#include <cstdint>

// Problem constants
#define S_DIM 8192
#define B_DIM 8192
#define ENC 256
#define C_DIM 25
#define K_RANK 25   // 0-based rank -> 26th smallest

// ------------------------------------------------------------------
// Scratch (device globals; allocation-free per harness rules)
// ------------------------------------------------------------------
__device__ __align__(256) float g_d2[(size_t)S_DIM * B_DIM];            // 268 MB
__device__ __align__(256) float g_ehi[(size_t)B_DIM * ENC];             // tf32(e)
__device__ __align__(256) float g_qhi[(size_t)S_DIM * ENC];             // gathered tf32(q)
__device__ __align__(256) __nv_bfloat16 g_ecA[(size_t)B_DIM * 2 * ENC]; // [qh16 | ql16] per b-row
__device__ __align__(256) __nv_bfloat16 g_ecB[(size_t)B_DIM * 2 * ENC]; // [el16 | eh16] per b-row
__device__ __align__(256) __nv_bfloat16 g_qcA[(size_t)S_DIM * 2 * ENC]; // gathered corr-A rows
__device__ float g_e2[B_DIM];
__device__ float g_q2[S_DIM];
__device__ float g_maxg[B_DIM];
__device__ unsigned char g_grp[B_DIM];

// ------------------------------------------------------------------
// Base-ISA PTX helpers (harness compiles via compute_103: NO 'a' features)
// ------------------------------------------------------------------
__device__ __forceinline__ uint32_t smem_u32(const void* p) {
    uint32_t a;
    asm("{ .reg .u64 t; cvta.to.shared.u64 t, %1; cvt.u32.u64 %0, t; }"
        : "=r"(a) : "l"(p));
    return a;
}
__device__ __forceinline__ float tf32_rn(float x) {
    uint32_t u;
    asm("cvt.rna.tf32.f32 %0, %1;" : "=r"(u) : "f"(x));
    return __uint_as_float(u);
}
__device__ __forceinline__ void cp16(uint32_t dst, const void* src) {
    asm volatile("cp.async.cg.shared.global [%0], [%1], 16;" :: "r"(dst), "l"(src));
}
__device__ __forceinline__ void ldsm4(uint32_t* r, uint32_t addr) {
    asm volatile("ldmatrix.sync.aligned.m8n8.x4.shared.b16 {%0,%1,%2,%3}, [%4];"
                 : "=r"(r[0]), "=r"(r[1]), "=r"(r[2]), "=r"(r[3]) : "r"(addr));
}
__device__ __forceinline__ void mma_tf32(float* c, const uint32_t* a, const uint32_t* b) {
    asm volatile(
        "mma.sync.aligned.m16n8k8.row.col.f32.tf32.tf32.f32 "
        "{%0,%1,%2,%3}, {%4,%5,%6,%7}, {%8,%9}, {%0,%1,%2,%3};"
        : "+f"(c[0]), "+f"(c[1]), "+f"(c[2]), "+f"(c[3])
        : "r"(a[0]), "r"(a[1]), "r"(a[2]), "r"(a[3]), "r"(b[0]), "r"(b[1]));
}
__device__ __forceinline__ void mma_bf16(float* c, const uint32_t* a, const uint32_t* b) {
    asm volatile(
        "mma.sync.aligned.m16n8k16.row.col.f32.bf16.bf16.f32 "
        "{%0,%1,%2,%3}, {%4,%5,%6,%7}, {%8,%9}, {%0,%1,%2,%3};"
        : "+f"(c[0]), "+f"(c[1]), "+f"(c[2]), "+f"(c[3])
        : "r"(a[0]), "r"(a[1]), "r"(a[2]), "r"(a[3]), "r"(b[0]), "r"(b[1]));
}
#define SWZ(o) ((o) ^ (((o) >> 3) & 0x70))

// ------------------------------------------------------------------
// Kernel 1: e2, argmax/max, tf32 + bf16 splits.  One block per b-row.
// ------------------------------------------------------------------
__global__ void prep_kernel(const float* __restrict__ enc,
                            const float* __restrict__ cat) {
    int b = blockIdx.x;
    int t = threadIdx.x;

    float v  = enc[(size_t)b * ENC + t];
    float hi = tf32_rn(v);
    float lo = v - hi;
    g_ehi[(size_t)b * ENC + t] = hi;
    __nv_bfloat16 h16 = __float2bfloat16(hi);
    __nv_bfloat16 l16 = __float2bfloat16(lo);
    g_ecA[(size_t)b * 2 * ENC + t]       = h16;   // qh16 slot
    g_ecA[(size_t)b * 2 * ENC + ENC + t] = l16;   // ql16 slot
    g_ecB[(size_t)b * 2 * ENC + t]       = l16;   // el16 slot
    g_ecB[(size_t)b * 2 * ENC + ENC + t] = h16;   // eh16 slot

    float sq = v * v;
    #pragma unroll
    for (int o = 16; o > 0; o >>= 1) sq += __shfl_xor_sync(0xFFFFFFFFu, sq, o);

    __shared__ float ws[8];
    if ((t & 31) == 0) ws[t >> 5] = sq;
    __syncthreads();
    if (t == 0) {
        float s = 0.f;
        #pragma unroll
        for (int i = 0; i < 8; i++) s += ws[i];
        g_e2[b] = s;
    }

    if (t < 32) {
        float mv = -1e30f;
        int   mi = 0x7FFFFFFF;
        if (t < C_DIM) { mv = cat[(size_t)b * C_DIM + t]; mi = t; }
        #pragma unroll
        for (int o = 16; o > 0; o >>= 1) {
            float ov = __shfl_xor_sync(0xFFFFFFFFu, mv, o);
            int   oi = __shfl_xor_sync(0xFFFFFFFFu, mi, o);
            if (ov > mv || (ov == mv && oi < mi)) { mv = ov; mi = oi; }
        }
        if (t == 0) { g_maxg[b] = mv; g_grp[b] = (unsigned char)mi; }
    }
}

// ------------------------------------------------------------------
// Kernel 2: gather q rows (tf32 + corrA) + q2
// ------------------------------------------------------------------
__global__ void gather_kernel(const int* __restrict__ idxs) {
    int s = blockIdx.x, t = threadIdx.x;   // 64 threads
    int idx = idxs[s];
    const float4* sh = reinterpret_cast<const float4*>(&g_ehi[(size_t)idx * ENC]);
    float4* dh = reinterpret_cast<float4*>(&g_qhi[(size_t)s * ENC]);
    dh[t] = sh[t];
    const uint4* sc = reinterpret_cast<const uint4*>(&g_ecA[(size_t)idx * 2 * ENC]);
    uint4* dc = reinterpret_cast<uint4*>(&g_qcA[(size_t)s * 2 * ENC]);
    dc[t] = sc[t];
    if (t == 0) g_q2[s] = g_e2[idx];
}

// ------------------------------------------------------------------
// Kernel 3: mixed tf32 + bf16 GEMM -> d2  (unchanged: proven)
// ------------------------------------------------------------------
#define BM 128
#define BN 256
#define NCHUNK 8
#define AF32_OFF 0
#define ACOR_OFF (128 * 128)                    // 16 KB
#define BF32_OFF (2 * 128 * 128)                // 32 KB
#define BCOR_OFF (BF32_OFF + 256 * 128)         // +32 KB
#define STAGE    (BCOR_OFF + 256 * 128)         // 96 KB
#define GEMM_SMEM (2 * STAGE)                   // 192 KB

__device__ __forceinline__ void load_stage(uint32_t st, int brow, int bcol,
                                           int c, int tid) {
    const char* qcA = reinterpret_cast<const char*>(g_qcA);
    const char* ecB = reinterpret_cast<const char*>(g_ecB);
    #pragma unroll
    for (int it = 0; it < 4; ++it) {
        int i = tid + it * 256;
        int r = i >> 3, ch = i & 7;
        uint32_t off = SWZ((uint32_t)(r * 128 + ch * 16));
        cp16(st + AF32_OFF + off, g_qhi + (size_t)(brow + r) * ENC + c * 32 + ch * 4);
        cp16(st + ACOR_OFF + off, qcA + (size_t)(brow + r) * 1024 + c * 128 + ch * 16);
    }
    #pragma unroll
    for (int it = 0; it < 8; ++it) {
        int i = tid + it * 256;
        int r = i >> 3, ch = i & 7;
        uint32_t off = SWZ((uint32_t)(r * 128 + ch * 16));
        cp16(st + BF32_OFF + off, g_ehi + (size_t)(bcol + r) * ENC + c * 32 + ch * 4);
        cp16(st + BCOR_OFF + off, ecB + (size_t)(bcol + r) * 1024 + c * 128 + ch * 16);
    }
    asm volatile("cp.async.commit_group;" ::: "memory");
}

__global__ __launch_bounds__(256, 1)
void dist_gemm_mma() {
    extern __shared__ char dsm_raw[];
    __shared__ float e2s[BN];
    __shared__ float q2s[BM];

    const int tid    = threadIdx.x;
    const int lane   = tid & 31;
    const int wid    = tid >> 5;
    const int warp_m = wid & 1;
    const int warp_n = wid >> 1;
    const int brow   = blockIdx.y * BM;
    const int bcol   = blockIdx.x * BN;

    const uint32_t dsm = smem_u32(dsm_raw);

    for (int i = tid; i < BN; i += 256) e2s[i] = g_e2[bcol + i];
    for (int i = tid; i < BM; i += 256) q2s[i] = g_q2[brow + i];

    float acc[4][8][4];
    #pragma unroll
    for (int im = 0; im < 4; im++)
        #pragma unroll
        for (int j = 0; j < 8; j++)
            #pragma unroll
            for (int v = 0; v < 4; v++) acc[im][j][v] = 0.f;

    const int a_row = warp_m * 64 + (lane & 15);
    const int a_kb  = (lane >> 4) << 4;
    const int b_row = warp_n * 64 + ((lane >> 4) << 3) + (lane & 7);
    const int b_kb  = ((lane >> 3) & 1) << 4;

    load_stage(dsm,         brow, bcol, 0, tid);
    load_stage(dsm + STAGE, brow, bcol, 1, tid);

    #pragma unroll
    for (int c = 0; c < NCHUNK; ++c) {
        if (c == NCHUNK - 1) asm volatile("cp.async.wait_group 0;" ::: "memory");
        else                 asm volatile("cp.async.wait_group 1;" ::: "memory");
        __syncthreads();

        const uint32_t st = dsm + (c & 1) * STAGE;

        #pragma unroll
        for (int ks = 0; ks < 4; ++ks) {
            uint32_t ahi[4][4], aco[4][4], bhi[8][2], bco[8][2];
            #pragma unroll
            for (int im = 0; im < 4; ++im) {
                uint32_t off = SWZ((uint32_t)((a_row + im * 16) * 128 + ks * 32 + a_kb));
                ldsm4(ahi[im], st + AF32_OFF + off);
                ldsm4(aco[im], st + ACOR_OFF + off);
            }
            #pragma unroll
            for (int jn = 0; jn < 4; ++jn) {
                uint32_t off = SWZ((uint32_t)((b_row + jn * 16) * 128 + ks * 32 + b_kb));
                uint32_t rh[4], rc[4];
                ldsm4(rh, st + BF32_OFF + off);
                ldsm4(rc, st + BCOR_OFF + off);
                bhi[2 * jn][0] = rh[0]; bhi[2 * jn][1] = rh[1];
                bhi[2 * jn + 1][0] = rh[2]; bhi[2 * jn + 1][1] = rh[3];
                bco[2 * jn][0] = rc[0]; bco[2 * jn][1] = rc[1];
                bco[2 * jn + 1][0] = rc[2]; bco[2 * jn + 1][1] = rc[3];
            }
            #pragma unroll
            for (int im = 0; im < 4; ++im)
                #pragma unroll
                for (int j = 0; j < 8; ++j) {
                    mma_tf32(acc[im][j], ahi[im], bhi[j]);
                    mma_bf16(acc[im][j], aco[im], bco[j]);
                }
        }
        __syncthreads();
        if (c + 2 < NCHUNK)
            load_stage(dsm + (c & 1) * STAGE, brow, bcol, c + 2, tid);
    }

    #pragma unroll
    for (int im = 0; im < 4; ++im) {
        const int r0 = warp_m * 64 + im * 16 + (lane >> 2);
        const float q2a = q2s[r0];
        const float q2b = q2s[r0 + 8];
        #pragma unroll
        for (int j = 0; j < 8; ++j) {
            const int cl = warp_n * 64 + j * 8 + 2 * (lane & 3);
            const float e0 = e2s[cl], e1 = e2s[cl + 1];
            float2 oa, ob;
            oa.x = fmaxf(fmaf(-2.f, acc[im][j][0], q2a + e0), 0.f);
            oa.y = fmaxf(fmaf(-2.f, acc[im][j][1], q2a + e1), 0.f);
            ob.x = fmaxf(fmaf(-2.f, acc[im][j][2], q2b + e0), 0.f);
            ob.y = fmaxf(fmaf(-2.f, acc[im][j][3], q2b + e1), 0.f);
            *reinterpret_cast<float2*>(&g_d2[(size_t)(brow + r0) * B_DIM + bcol + cl]) = oa;
            *reinterpret_cast<float2*>(&g_d2[(size_t)(brow + r0 + 8) * B_DIM + bcol + cl]) = ob;
        }
    }
}

// ------------------------------------------------------------------
// Kernel 4 (v5): threshold-count select. Exact.
//  - Row in registers; NO histogram, NO per-value atomics.
//  - Bound B0 = max of 8 warp-mins (rank ~8-40); grow by +2^20 bits
//    (x1.09) until cnt >= 26; binary-refine if cnt > CAP (rare).
//  - Collect candidates once; O(m^2) exact rank-25; bincount on hits.
// ------------------------------------------------------------------
#define CAND_CAP 2048

__global__ __launch_bounds__(256)
void select_kernel(const int* __restrict__ idxs, float* __restrict__ out) {
    const int s    = blockIdx.x;
    const int tid  = threadIdx.x;
    const int lane = tid & 31;
    const int wid  = tid >> 5;

    __shared__ uint32_t cand_v[CAND_CAP];     // 8 KB
    __shared__ uint32_t cand_i[CAND_CAP];     // 8 KB
    __shared__ uint32_t wred[8];
    __shared__ uint32_t sh_m;
    __shared__ uint32_t sh_kbits;
    __shared__ int counts[C_DIM];

    // Load row into registers (coalesced uint4); all values >= 0.
    const uint4* row4 = reinterpret_cast<const uint4*>(g_d2 + (size_t)s * B_DIM);
    uint4 v[8];
    #pragma unroll
    for (int k = 0; k < 8; k++) v[k] = row4[tid + k * 256];

    // Block bound B0 = max over warps of warp-min
    uint32_t mn = 0xFFFFFFFFu;
    #pragma unroll
    for (int k = 0; k < 8; k++)
        mn = min(mn, min(min(v[k].x, v[k].y), min(v[k].z, v[k].w)));
    #pragma unroll
    for (int o = 16; o > 0; o >>= 1)
        mn = min(mn, __shfl_xor_sync(0xFFFFFFFFu, mn, o));
    if (lane == 0) wred[wid] = mn;
    __syncthreads();
    uint32_t B = 0;
    #pragma unroll
    for (int w = 0; w < 8; w++) B = max(B, wred[w]);
    if (B == 0) B = 0x7F800000u;   // degenerate: use +inf bits
    __syncthreads();

    // count of values strictly below X (uniform across block)
    auto count_lt = [&](uint32_t X) -> int {
        int c = 0;
        #pragma unroll
        for (int k = 0; k < 8; k++)
            c += (int)(v[k].x < X) + (int)(v[k].y < X) +
                 (int)(v[k].z < X) + (int)(v[k].w < X);
        #pragma unroll
        for (int o = 16; o > 0; o >>= 1)
            c += __shfl_xor_sync(0xFFFFFFFFu, c, o);
        if (lane == 0) wred[wid] = (uint32_t)c;
        __syncthreads();
        int t = 0;
        #pragma unroll
        for (int w = 0; w < 8; w++) t += (int)wred[w];
        __syncthreads();
        return t;
    };

    int cnt = count_lt(B);

    // Grow bound until it covers rank 25 (expected 0-2 iterations)
    int guard = 0;
    while (cnt < 26 && guard < 64) {
        B += (1u << 20);           // x1.09 in value
        cnt = count_lt(B);
        guard++;
    }
    if (cnt < 26) { B = 0x7F800000u; cnt = count_lt(B); }

    // Shrink if too many candidates (rare): binary search on bit values
    uint32_t lo = 0;
    bool direct = false;           // stuck pair: kth bits == lo exactly
    while (cnt > CAND_CAP) {
        uint32_t mid = lo + ((B - lo) >> 1);
        if (mid == lo) { direct = true; break; }
        int c = count_lt(mid);
        if (c >= 26) { B = mid; cnt = c; }
        else         { lo = mid; }
    }

    // Collect candidates (value + column) below the final bound
    if (tid == 0) sh_m = 0;
    __syncthreads();
    const uint32_t bound = direct ? lo : B;
    #pragma unroll
    for (int k = 0; k < 8; k++) {
        uint32_t vv[4] = {v[k].x, v[k].y, v[k].z, v[k].w};
        #pragma unroll
        for (int j = 0; j < 4; j++) {
            if (vv[j] < bound) {
                uint32_t p = atomicAdd(&sh_m, 1u);
                cand_v[p] = vv[j];
                cand_i[p] = 4u * (uint32_t)(tid + k * 256) + (uint32_t)j;
            }
        }
    }
    if (tid < C_DIM) counts[tid] = 0;
    __syncthreads();
    const int m = (int)sh_m;

    // Exact rank-25 among candidates (skip if degenerate-direct)
    if (!direct) {
        for (int i = tid; i < m; i += 256) {
            uint32_t vi = cand_v[i];
            int l = 0, e = 0;
            for (int j = 0; j < m; j++) {
                uint32_t vj = cand_v[j];
                l += (vj < vi);
                e += (vj == vi);
            }
            if (l <= K_RANK && K_RANK < l + e) sh_kbits = vi;
        }
    } else if (tid == 0) {
        sh_kbits = lo;
    }
    __syncthreads();
    const uint32_t kbits = sh_kbits;

    // Bincount of neighbours (v < kbits); label fetch only on hits (~25)
    for (int i = tid; i < m; i += 256) {
        if (cand_v[i] < kbits)
            atomicAdd(&counts[g_grp[cand_i[i]]], 1);
    }
    __syncthreads();

    if (tid == 0) {
        int n = 0;
        #pragma unroll
        for (int c = 0; c < C_DIM; c++) n += counts[c];
        float inv = 1.0f / (float)n;
        float purity = 0.f;
        #pragma unroll
        for (int c = 0; c < C_DIM; c++) {
            float p = (float)counts[c] * inv;
            purity -= p * logf(p + 1e-5f);
        }
        out[s] = purity * g_maxg[idxs[s]];
    }
}

// ------------------------------------------------------------------
// Launch
// ------------------------------------------------------------------
extern "C" void kernel_launch(void* const* d_in, const int* in_sizes, int n_in,
                              void* d_out, int out_size) {
    const float* enc  = (const float*)d_in[0];
    const float* cat  = (const float*)d_in[1];
    const int*   idxs = (const int*)d_in[2];
    float* out = (float*)d_out;

    static bool attr_done = false;
    if (!attr_done) {
        cudaFuncSetAttribute(dist_gemm_mma,
                             cudaFuncAttributeMaxDynamicSharedMemorySize, GEMM_SMEM);
        attr_done = true;
    }

    prep_kernel<<<B_DIM, 256>>>(enc, cat);
    gather_kernel<<<S_DIM, 64>>>(idxs);

    dim3 grid(B_DIM / BN, S_DIM / BM);
    dist_gemm_mma<<<grid, 256, GEMM_SMEM>>>();

    select_kernel<<<S_DIM, 256>>>(idxs, out);
}